// round 8
// baseline (speedup 1.0000x reference)
#include <cuda_runtime.h>
#include <cstdint>

// KV cache update:
//   kv_cache: (2L, B, H, S, D) fp32, L=2,B=8,H=8,S=4096,D=128
//   new_kv:   (L, 2, B, H, 1, D) fp32
//   position_ids: (B, 1)  -- int64 in source, possibly serialized as int32
// out = kv_cache with out[2l+kv, b, h, pos[b], :] = new_kv[l, kv, b, h, 0, :]
//
// Single fused streaming kernel (memory-roofline bound: 1 GiB mandatory traffic).
// 8 x float4 per thread front-batched (MLP=8), TPB=256, min 6 blocks/SM
// (forces <=42 regs -> 48 resident warps/SM for deeper latency hiding).

static constexpr unsigned Bv  = 8;
static constexpr unsigned Hv  = 8;
static constexpr unsigned Sv  = 4096;
static constexpr unsigned D4  = 128 / 4;                   // float4 per row
static constexpr unsigned N4  = 4u * Bv * Hv * Sv * D4;    // 2^25 float4 total

static constexpr unsigned VPT  = 8;                        // float4 per thread (128 B)
static constexpr unsigned TPB  = 256;
static constexpr unsigned NBLK = N4 / (VPT * TPB);         // 16384

// Robustly fetch pos[b] whether the buffer is int32[8] or int64[8] (LE).
// Positions are in [0, 4096) so int64 high words are all zero; for int32 data
// the odd words are random positions (P(all zero) ~ 4096^-4, negligible).
__device__ __forceinline__ int load_pos(const int* __restrict__ pw, unsigned b)
{
    bool is64 = true;
#pragma unroll
    for (int i = 0; i < 8; ++i)
        is64 &= (pw[2 * i + 1] == 0);
    return is64 ? pw[2 * b] : pw[b];
}

__global__ void __launch_bounds__(TPB, 6)
kv_fused_kernel(const float4* __restrict__ src,
                const float4* __restrict__ newkv,
                const int*    __restrict__ posw,
                float4*       __restrict__ dst)
{
    // Block covers a contiguous span of VPT*TPB = 2048 float4s = 64 rows.
    // Layout [lkv][b][h][s][d4]: lkv/b/h (bits >= 17) are block-constant.
    unsigned base = blockIdx.x * (VPT * TPB) + threadIdx.x;

    unsigned lkv = base >> 23;
    unsigned b   = (base >> 20) & 7u;
    unsigned h   = (base >> 17) & 7u;

    int p = load_pos(posw, b);                              // L1-resident
    unsigned rowbase = ((lkv * 8u + b) * 8u + h) * 32u;     // new_kv row offset

    float4 v[VPT];
#pragma unroll
    for (unsigned j = 0; j < VPT; ++j)                      // front-batched: MLP=8
        v[j] = __ldcs(&src[base + j * TPB]);

#pragma unroll
    for (unsigned j = 0; j < VPT; ++j) {
        unsigned idx = base + j * TPB;
        unsigned s = (idx >> 5) & 4095u;
        if ((int)s == p)
            v[j] = newkv[rowbase + (idx & 31u)];
        __stcs(&dst[idx], v[j]);
    }
}

extern "C" void kernel_launch(void* const* d_in, const int* in_sizes, int n_in,
                              void* d_out, int out_size)
{
    const float4* cache = (const float4*)d_in[0];
    const float4* newkv = (const float4*)d_in[1];
    const int*    posw  = (const int*)d_in[2];
    float4*       out   = (float4*)d_out;

    kv_fused_kernel<<<NBLK, TPB>>>(cache, newkv, posw, out);
}

// round 9
// speedup vs baseline: 1.0039x; 1.0039x over previous
#include <cuda_runtime.h>
#include <cstdint>

// KV cache update:
//   kv_cache: (2L, B, H, S, D) fp32, L=2,B=8,H=8,S=4096,D=128
//   new_kv:   (L, 2, B, H, 1, D) fp32
//   position_ids: (B, 1)  -- int64 in source, possibly serialized as int32
// out = kv_cache with out[2l+kv, b, h, pos[b], :] = new_kv[l, kv, b, h, 0, :]
//
// FINAL (R5 configuration — best of 6 measured variants):
// Single fused streaming kernel at the HBM roofline: 1 GiB mandatory traffic,
// 6.8 TB/s sustained (86% of 8 TB/s spec). 8 x float4 per thread, loads
// front-batched for MLP=8, evict-first cache hints, scatter fused via
// predication (lkv/b/h are block-constant; pos[b] is L1-resident).

static constexpr unsigned Bv  = 8;
static constexpr unsigned Hv  = 8;
static constexpr unsigned Sv  = 4096;
static constexpr unsigned D4  = 128 / 4;                   // float4 per row
static constexpr unsigned N4  = 4u * Bv * Hv * Sv * D4;    // 2^25 float4 total

static constexpr unsigned VPT  = 8;                        // float4 per thread (128 B)
static constexpr unsigned TPB  = 256;
static constexpr unsigned NBLK = N4 / (VPT * TPB);         // 16384

// Robustly fetch pos[b] whether the buffer is int32[8] or int64[8] (LE).
// Positions are in [0, 4096) so int64 high words are all zero; for int32 data
// the odd words are random positions (P(all zero) ~ 4096^-4, negligible).
__device__ __forceinline__ int load_pos(const int* __restrict__ pw, unsigned b)
{
    bool is64 = true;
#pragma unroll
    for (int i = 0; i < 8; ++i)
        is64 &= (pw[2 * i + 1] == 0);
    return is64 ? pw[2 * b] : pw[b];
}

__global__ void __launch_bounds__(TPB)
kv_fused_kernel(const float4* __restrict__ src,
                const float4* __restrict__ newkv,
                const int*    __restrict__ posw,
                float4*       __restrict__ dst)
{
    // Block covers a contiguous span of VPT*TPB = 2048 float4s = 64 rows.
    // Layout [lkv][b][h][s][d4]: lkv/b/h (bits >= 17) are block-constant.
    unsigned base = blockIdx.x * (VPT * TPB) + threadIdx.x;

    unsigned lkv = base >> 23;
    unsigned b   = (base >> 20) & 7u;
    unsigned h   = (base >> 17) & 7u;

    int p = load_pos(posw, b);                              // L1-resident
    unsigned rowbase = ((lkv * 8u + b) * 8u + h) * 32u;     // new_kv row offset

    float4 v[VPT];
#pragma unroll
    for (unsigned j = 0; j < VPT; ++j)                      // front-batched: MLP=8
        v[j] = __ldcs(&src[base + j * TPB]);

#pragma unroll
    for (unsigned j = 0; j < VPT; ++j) {
        unsigned idx = base + j * TPB;
        unsigned s = (idx >> 5) & 4095u;
        if ((int)s == p)
            v[j] = newkv[rowbase + (idx & 31u)];
        __stcs(&dst[idx], v[j]);
    }
}

extern "C" void kernel_launch(void* const* d_in, const int* in_sizes, int n_in,
                              void* d_out, int out_size)
{
    const float4* cache = (const float4*)d_in[0];
    const float4* newkv = (const float4*)d_in[1];
    const int*    posw  = (const int*)d_in[2];
    float4*       out   = (float4*)d_out;

    kv_fused_kernel<<<NBLK, TPB>>>(cache, newkv, posw, out);
}

// round 11
// speedup vs baseline: 1.0121x; 1.0082x over previous
#include <cuda_runtime.h>
#include <cstdint>

// KV cache update:
//   kv_cache: (2L, B, H, S, D) fp32, L=2,B=8,H=8,S=4096,D=128
//   new_kv:   (L, 2, B, H, 1, D) fp32
//   position_ids: (B, 1)  -- int64 in source, possibly serialized as int32
// out = kv_cache with out[2l+kv, b, h, pos[b], :] = new_kv[l, kv, b, h, 0, :]
//
// FINAL — converged at the HBM roofline (best of 7 measured variants):
//   CE memcpy            ~340 us   (copy engine caps at ~3.1 TB/s)
//   VPT=4 /TPB=256        154.2 us  83.8% DRAM
//   VPT=8 /TPB=256        149.4 us  86.0% DRAM   <== this kernel
//   VPT=16/TPB=256        150.8 us  85.2% DRAM  (reg pressure kills occupancy)
//   VPT=8 /TPB=128        150.9 us  85.2% DRAM
//   VPT=8 /256/minb=6     152.9 us  84.3% DRAM  (reg cap breaks load batching)
// 1 GiB mandatory traffic at ~6.8 TB/s sustained (86% of 8 TB/s spec).
// 8 x float4 per thread, loads front-batched for MLP=8, evict-first cache
// hints, scatter fused via predication (lkv/b/h block-constant, pos[b] L1-hit).

static constexpr unsigned Bv  = 8;
static constexpr unsigned Hv  = 8;
static constexpr unsigned Sv  = 4096;
static constexpr unsigned D4  = 128 / 4;                   // float4 per row
static constexpr unsigned N4  = 4u * Bv * Hv * Sv * D4;    // 2^25 float4 total

static constexpr unsigned VPT  = 8;                        // float4 per thread (128 B)
static constexpr unsigned TPB  = 256;
static constexpr unsigned NBLK = N4 / (VPT * TPB);         // 16384

// Robustly fetch pos[b] whether the buffer is int32[8] or int64[8] (LE).
// Positions are in [0, 4096) so int64 high words are all zero; for int32 data
// the odd words are random positions (P(all zero) ~ 4096^-4, negligible).
__device__ __forceinline__ int load_pos(const int* __restrict__ pw, unsigned b)
{
    bool is64 = true;
#pragma unroll
    for (int i = 0; i < 8; ++i)
        is64 &= (pw[2 * i + 1] == 0);
    return is64 ? pw[2 * b] : pw[b];
}

__global__ void __launch_bounds__(TPB)
kv_fused_kernel(const float4* __restrict__ src,
                const float4* __restrict__ newkv,
                const int*    __restrict__ posw,
                float4*       __restrict__ dst)
{
    // Block covers a contiguous span of VPT*TPB = 2048 float4s = 64 rows.
    // Layout [lkv][b][h][s][d4]: lkv/b/h (bits >= 17) are block-constant.
    unsigned base = blockIdx.x * (VPT * TPB) + threadIdx.x;

    unsigned lkv = base >> 23;
    unsigned b   = (base >> 20) & 7u;
    unsigned h   = (base >> 17) & 7u;

    int p = load_pos(posw, b);                              // L1-resident
    unsigned rowbase = ((lkv * 8u + b) * 8u + h) * 32u;     // new_kv row offset

    float4 v[VPT];
#pragma unroll
    for (unsigned j = 0; j < VPT; ++j)                      // front-batched: MLP=8
        v[j] = __ldcs(&src[base + j * TPB]);

#pragma unroll
    for (unsigned j = 0; j < VPT; ++j) {
        unsigned idx = base + j * TPB;
        unsigned s = (idx >> 5) & 4095u;
        if ((int)s == p)
            v[j] = newkv[rowbase + (idx & 31u)];
        __stcs(&dst[idx], v[j]);
    }
}

extern "C" void kernel_launch(void* const* d_in, const int* in_sizes, int n_in,
                              void* d_out, int out_size)
{
    const float4* cache = (const float4*)d_in[0];
    const float4* newkv = (const float4*)d_in[1];
    const int*    posw  = (const int*)d_in[2];
    float4*       out   = (float4*)d_out;

    kv_fused_kernel<<<NBLK, TPB>>>(cache, newkv, posw, out);
}